// round 12
// baseline (speedup 1.0000x reference)
#include <cuda_runtime.h>
#include <cuda_fp16.h>
#include <cstdint>

#define DEVINL __device__ __forceinline__

DEVINL uint32_t smem_u32(const void* p) {
    uint32_t a;
    asm("{ .reg .u64 t; cvta.to.shared.u64 t, %1; cvt.u32.u64 %0, t; }"
        : "=r"(a) : "l"(p));
    return a;
}

// 128B-row swizzle — verified conflict-free for ldmatrix.x4
#define SWZ(o) ((o) ^ (((o) >> 3) & 0x70))

DEVINL void ldsm_x4(uint32_t& r0, uint32_t& r1, uint32_t& r2, uint32_t& r3, uint32_t addr) {
    asm volatile("ldmatrix.sync.aligned.m8n8.x4.shared.b16 {%0,%1,%2,%3}, [%4];"
                 : "=r"(r0), "=r"(r1), "=r"(r2), "=r"(r3) : "r"(addr));
}

DEVINL void mma_16816(float* c, uint32_t a0, uint32_t a1, uint32_t a2, uint32_t a3,
                      uint32_t b0, uint32_t b1) {
    asm volatile(
        "mma.sync.aligned.m16n8k16.row.col.f32.f16.f16.f32 "
        "{%0,%1,%2,%3}, {%4,%5,%6,%7}, {%8,%9}, {%0,%1,%2,%3};"
        : "+f"(c[0]), "+f"(c[1]), "+f"(c[2]), "+f"(c[3])
        : "r"(a0), "r"(a1), "r"(a2), "r"(a3), "r"(b0), "r"(b1));
}

DEVINL void cp_async16(uint32_t smem_addr, const void* gptr) {
    asm volatile("cp.async.cg.shared.global [%0], [%1], 16;"
                 :: "r"(smem_addr), "l"(gptr));
}
#define CP_COMMIT() asm volatile("cp.async.commit_group;" ::: "memory")
#define CP_WAIT(n)  asm volatile("cp.async.wait_group %0;" :: "n"(n) : "memory")

DEVINL uint32_t packh2(float a, float b) {
    __half2 h = __floats2half2_rn(a, b);
    return *reinterpret_cast<uint32_t*>(&h);
}

// ============================================================================
// Problem constants
// ============================================================================
static constexpr int N_ROWS  = 262144;
static constexpr int M_TILE  = 128;
static constexpr int N_CTAS  = N_ROWS / M_TILE;  // 2048
static constexpr int THREADS = 512;              // 16 warps, 4m x 4n, 32x64 tiles

// fp16 transposed weights (scratch via device globals)
__device__ __align__(16) __half w1h_g[512 * 1024];  // [N=512][K=1024]
__device__ __align__(16) __half w2h_g[256 * 512];   // [N=256][K=512]

// ---------------- SMEM layout (bytes) ----------------
static constexpr int SM_COORD = 0;       // 128 x float2          = 1024
static constexpr int SM_W0    = 1024;    // 2048 f32              = 8192
static constexpr int SM_B0    = 9216;    // 1024 f32              = 4096
static constexpr int SM_B1    = 13312;   // 512 f32               = 2048
static constexpr int SM_B2    = 15360;   // 256 f32               = 1024
static constexpr int SM_W3    = 16384;   // 768 f32               = 3072  -> 19456
static constexpr int SM_H2    = 19456;   // 8 blocks x 16KB       = 131072 -> 150528
static constexpr int SM_PART  = 150528;  // 4 x 384 f32 (layer-3 partials)
static constexpr int SM_BCH0  = 166912;  // 256x64 fp16 SWZ128    = 32768 -> 199680
static constexpr int SM_BCH1  = 199680;  // 256x64 fp16 SWZ128    = 32768 -> 232448
static constexpr int SMEM_TOTAL = 232448;

// ============================================================================
// Prep: transpose + fp16-convert W1, W2
// ============================================================================
__global__ void prep_weights(const float* __restrict__ W1, const float* __restrict__ W2) {
    int i = blockIdx.x * blockDim.x + threadIdx.x;
    if (i < 512 * 1024) {
        int n = i >> 10, k = i & 1023;
        w1h_g[i] = __float2half_rn(W1[k * 512 + n]);
    } else {
        int j = i - 512 * 1024;
        if (j < 256 * 512) {
            int n = j >> 9, k = j & 511;
            w2h_g[j] = __float2half_rn(W2[k * 256 + n]);
        }
    }
}

// ============================================================================
// Fused MLP: one CTA = 128 rows; 16 warps; layer-1 A computed in registers
// ============================================================================
__global__ __launch_bounds__(THREADS, 1) void fused_mlp_kernel(
    const float* __restrict__ coord,
    const float* __restrict__ W0, const float* __restrict__ b0,
    const float* __restrict__ b1, const float* __restrict__ b2,
    const float* __restrict__ W3, const float* __restrict__ b3,
    float* __restrict__ out)
{
    extern __shared__ char smem[];
    const uint32_t sb = smem_u32(smem);
    const int tid  = threadIdx.x;
    const int wid  = tid >> 5;
    const int lane = tid & 31;
    const int row0 = blockIdx.x * M_TILE;

    float* sCoord = (float*)(smem + SM_COORD);
    float* sW0    = (float*)(smem + SM_W0);
    float* sB0    = (float*)(smem + SM_B0);
    float* sB1    = (float*)(smem + SM_B1);
    float* sB2    = (float*)(smem + SM_B2);
    float* sW3    = (float*)(smem + SM_W3);
    float* sPart  = (float*)(smem + SM_PART);

    // ---- preload constants + coord tile ----
    if (tid < 256) sCoord[tid] = coord[row0 * 2 + tid];
    for (int i = tid; i < 2048; i += THREADS) sW0[i] = W0[i];
    for (int i = tid; i < 1024; i += THREADS) sB0[i] = b0[i];
    if (tid < 512) sB1[tid] = b1[tid];
    if (tid < 256) sB2[tid] = b2[tid];
    for (int i = tid; i < 768;  i += THREADS) sW3[i] = W3[i];

    // ---- per-warp tile geometry: 4 row groups x 4 col groups ----
    const int m0  = (wid >> 2) * 32;    // warp row base (32 rows)
    const int n0w = (wid & 3) * 64;     // warp col base within a 256-col pass

    const int a_row = (lane & 7) + ((lane >> 3) & 1) * 8;
    const int a_kby = ((lane >> 4) & 1) * 16;
    const int b_row = (lane & 7) + ((lane >> 4) & 1) * 8;
    const int b_kby = ((lane >> 3) & 1) * 16;

    // B-chunk async copy: 2048 x 16B per chunk over 512 threads -> 4 each
    const int rowb = tid >> 3;           // 0..63, stride 64 across ii
    const int seg  = tid & 7;

    // prologue: first B1 chunk (pass 0, kc 0) into buffer 0
    {
        const __half* src = w1h_g + rowb * 1024 + seg * 8;
        #pragma unroll
        for (int ii = 0; ii < 4; ++ii)
            cp_async16(sb + SM_BCH0 + SWZ((uint32_t)((rowb + 64 * ii) * 128 + seg * 16)),
                       src + (64 * ii) * 1024);
        CP_COMMIT();
    }
    __syncthreads();   // constants + coord visible

    // ---- per-lane coord values for the 4 A-frag rows this lane owns ----
    const int q = lane >> 2;
    float cxr[2][2], cyr[2][2];
    #pragma unroll
    for (int f = 0; f < 2; ++f)
        #pragma unroll
        for (int h = 0; h < 2; ++h) {
            const int r = m0 + f * 16 + h * 8 + q;
            cxr[f][h] = sCoord[2 * r];
            cyr[f][h] = sCoord[2 * r + 1];
        }
    const int cl = (lane & 3) * 2;   // k column pair base within a 16-k step

    // =========================================================================
    // Layer 0+1: D1[128,512] = relu(coord@W0+b0) @ W1, two 256-col passes
    //            A fragments computed per-lane in registers (no smem A)
    // =========================================================================
    for (int pass = 0; pass < 2; ++pass) {
        float acc[2][8][4];
        #pragma unroll
        for (int i = 0; i < 2; ++i)
            #pragma unroll
            for (int j = 0; j < 8; ++j)
                #pragma unroll
                for (int qq = 0; qq < 4; ++qq) acc[i][j][qq] = 0.f;

        for (int kc = 0; kc < 16; ++kc) {
            const uint32_t bcur = (kc & 1) ? SM_BCH1 : SM_BCH0;
            const uint32_t bnxt = (kc & 1) ? SM_BCH0 : SM_BCH1;
            __syncthreads();  // buffer-reuse fence (prev MMA reads done)

            const bool last = (pass == 1) && (kc == 15);
            if (kc < 15) {
                const int j0n = (kc + 1) * 64;
                const __half* src = w1h_g + (pass * 256 + rowb) * 1024 + j0n + seg * 8;
                #pragma unroll
                for (int ii = 0; ii < 4; ++ii)
                    cp_async16(sb + bnxt + SWZ((uint32_t)((rowb + 64 * ii) * 128 + seg * 16)),
                               src + (64 * ii) * 1024);
                CP_COMMIT();
            } else if (pass == 0) {
                const __half* src = w1h_g + (256 + rowb) * 1024 + seg * 8;
                #pragma unroll
                for (int ii = 0; ii < 4; ++ii)
                    cp_async16(sb + bnxt + SWZ((uint32_t)((rowb + 64 * ii) * 128 + seg * 16)),
                               src + (64 * ii) * 1024);
                CP_COMMIT();
            }

            // --- compute A fragments for all 4 k-steps (overlaps B flight) ---
            uint32_t Areg[4][2][4];
            #pragma unroll
            for (int ks = 0; ks < 4; ++ks) {
                const int c = kc * 64 + ks * 16 + cl;
                const float x0 = sW0[c],        x1 = sW0[c + 1];
                const float x8 = sW0[c + 8],    x9 = sW0[c + 9];
                const float y0 = sW0[1024 + c], y1 = sW0[1025 + c];
                const float y8 = sW0[1032 + c], y9 = sW0[1033 + c];
                const float z0 = sB0[c],        z1 = sB0[c + 1];
                const float z8 = sB0[c + 8],    z9 = sB0[c + 9];
                #pragma unroll
                for (int f = 0; f < 2; ++f) {
                    const float ax = cxr[f][0], ay = cyr[f][0];
                    const float bx = cxr[f][1], by = cyr[f][1];
                    const float va0 = fmaxf(fmaf(ax, x0, fmaf(ay, y0, z0)), 0.f);
                    const float va1 = fmaxf(fmaf(ax, x1, fmaf(ay, y1, z1)), 0.f);
                    const float va8 = fmaxf(fmaf(ax, x8, fmaf(ay, y8, z8)), 0.f);
                    const float va9 = fmaxf(fmaf(ax, x9, fmaf(ay, y9, z9)), 0.f);
                    const float vb0 = fmaxf(fmaf(bx, x0, fmaf(by, y0, z0)), 0.f);
                    const float vb1 = fmaxf(fmaf(bx, x1, fmaf(by, y1, z1)), 0.f);
                    const float vb8 = fmaxf(fmaf(bx, x8, fmaf(by, y8, z8)), 0.f);
                    const float vb9 = fmaxf(fmaf(bx, x9, fmaf(by, y9, z9)), 0.f);
                    Areg[ks][f][0] = packh2(va0, va1);
                    Areg[ks][f][1] = packh2(vb0, vb1);
                    Areg[ks][f][2] = packh2(va8, va9);
                    Areg[ks][f][3] = packh2(vb8, vb9);
                }
            }

            if (last) { CP_WAIT(0); } else { CP_WAIT(1); }
            __syncthreads();  // B(kc) visible to all

            // --- 4 k-steps of mma: B from smem, A from registers ---
            #pragma unroll
            for (int ks = 0; ks < 4; ++ks) {
                const int kby = ks * 32;
                #pragma unroll
                for (int j2 = 0; j2 < 4; ++j2) {
                    uint32_t bb[4];
                    ldsm_x4(bb[0], bb[1], bb[2], bb[3],
                            sb + bcur + SWZ((uint32_t)((n0w + j2 * 16 + b_row) * 128 + kby + b_kby)));
                    mma_16816(acc[0][2 * j2],     Areg[ks][0][0], Areg[ks][0][1], Areg[ks][0][2], Areg[ks][0][3], bb[0], bb[1]);
                    mma_16816(acc[0][2 * j2 + 1], Areg[ks][0][0], Areg[ks][0][1], Areg[ks][0][2], Areg[ks][0][3], bb[2], bb[3]);
                    mma_16816(acc[1][2 * j2],     Areg[ks][1][0], Areg[ks][1][1], Areg[ks][1][2], Areg[ks][1][3], bb[0], bb[1]);
                    mma_16816(acc[1][2 * j2 + 1], Areg[ks][1][0], Areg[ks][1][1], Areg[ks][1][2], Areg[ks][1][3], bb[2], bb[3]);
                }
            }

            if (last) {
                // prologue for layer-2 (kc=15 -> bcur=BCH1, BCH0 free)
                const __half* src = w2h_g + rowb * 512 + seg * 8;
                #pragma unroll
                for (int ii = 0; ii < 4; ++ii)
                    cp_async16(sb + SM_BCH0 + SWZ((uint32_t)((rowb + 64 * ii) * 128 + seg * 16)),
                               src + (64 * ii) * 512);
                CP_COMMIT();
            }
        }

        // --- epilogue: h2 = relu(D1 + b1) -> fp16 H2 (8 x 16KB blocks) ---
        const int cn = pass * 256 + n0w;
        #pragma unroll
        for (int i = 0; i < 2; ++i) {
            const int r = m0 + i * 16 + (lane >> 2);
            #pragma unroll
            for (int j = 0; j < 8; ++j) {
                const int c = cn + j * 8 + (lane & 3) * 2;
                const float bz0 = sB1[c], bz1 = sB1[c + 1];
                float v0 = fmaxf(acc[i][j][0] + bz0, 0.f);
                float v1 = fmaxf(acc[i][j][1] + bz1, 0.f);
                float v2 = fmaxf(acc[i][j][2] + bz0, 0.f);
                float v3 = fmaxf(acc[i][j][3] + bz1, 0.f);
                const int blk = c >> 6, jj = (c & 63) * 2;
                *(__half2*)(smem + SM_H2 + blk * 16384 + SWZ((uint32_t)(r * 128 + jj))) =
                    __floats2half2_rn(v0, v1);
                *(__half2*)(smem + SM_H2 + blk * 16384 + SWZ((uint32_t)((r + 8) * 128 + jj))) =
                    __floats2half2_rn(v2, v3);
            }
        }
    }

    // =========================================================================
    // Layer 2: D2[128,256] = h2[128,512] @ W2 (A resident in SM_H2, ldmatrix)
    // =========================================================================
    float acc2[2][8][4];
    #pragma unroll
    for (int i = 0; i < 2; ++i)
        #pragma unroll
        for (int j = 0; j < 8; ++j)
            #pragma unroll
            for (int qq = 0; qq < 4; ++qq) acc2[i][j][qq] = 0.f;

    for (int kc = 0; kc < 8; ++kc) {
        const uint32_t bcur = (kc & 1) ? SM_BCH1 : SM_BCH0;
        const uint32_t bnxt = (kc & 1) ? SM_BCH0 : SM_BCH1;
        __syncthreads();  // buffer-reuse fence + (kc==0) h2-write fence

        if (kc < 7) {
            const __half* src = w2h_g + rowb * 512 + (kc + 1) * 64 + seg * 8;
            #pragma unroll
            for (int ii = 0; ii < 4; ++ii)
                cp_async16(sb + bnxt + SWZ((uint32_t)((rowb + 64 * ii) * 128 + seg * 16)),
                           src + (64 * ii) * 512);
            CP_COMMIT();
            CP_WAIT(1);
        } else {
            CP_WAIT(0);
        }
        __syncthreads();

        const uint32_t abase = sb + SM_H2 + kc * 16384;
        #pragma unroll
        for (int ks = 0; ks < 4; ++ks) {
            const int kby = ks * 32;
            uint32_t A0[4], A1f[4];
            ldsm_x4(A0[0], A0[1], A0[2], A0[3],
                    abase + SWZ((uint32_t)((m0 + a_row) * 128 + kby + a_kby)));
            ldsm_x4(A1f[0], A1f[1], A1f[2], A1f[3],
                    abase + SWZ((uint32_t)((m0 + 16 + a_row) * 128 + kby + a_kby)));
            #pragma unroll
            for (int j2 = 0; j2 < 4; ++j2) {
                uint32_t bb[4];
                ldsm_x4(bb[0], bb[1], bb[2], bb[3],
                        sb + bcur + SWZ((uint32_t)((n0w + j2 * 16 + b_row) * 128 + kby + b_kby)));
                mma_16816(acc2[0][2 * j2],     A0[0],  A0[1],  A0[2],  A0[3],  bb[0], bb[1]);
                mma_16816(acc2[0][2 * j2 + 1], A0[0],  A0[1],  A0[2],  A0[3],  bb[2], bb[3]);
                mma_16816(acc2[1][2 * j2],     A1f[0], A1f[1], A1f[2], A1f[3], bb[0], bb[1]);
                mma_16816(acc2[1][2 * j2 + 1], A1f[0], A1f[1], A1f[2], A1f[3], bb[2], bb[3]);
            }
        }
    }

    // =========================================================================
    // Layer 3: out = relu(D2 + b2) @ W3 + b3, from register fragments
    // =========================================================================
    float p[2][2][3];
    #pragma unroll
    for (int i = 0; i < 2; ++i)
        #pragma unroll
        for (int h = 0; h < 2; ++h)
            p[i][h][0] = p[i][h][1] = p[i][h][2] = 0.f;

    #pragma unroll
    for (int i = 0; i < 2; ++i) {
        #pragma unroll
        for (int j = 0; j < 8; ++j) {
            const int c = n0w + j * 8 + (lane & 3) * 2;
            #pragma unroll
            for (int qq = 0; qq < 4; ++qq) {
                const int h  = qq >> 1;
                const int cc = c + (qq & 1);
                const float v = fmaxf(acc2[i][j][qq] + sB2[cc], 0.f);
                p[i][h][0] = fmaf(v, sW3[cc * 3 + 0], p[i][h][0]);
                p[i][h][1] = fmaf(v, sW3[cc * 3 + 1], p[i][h][1]);
                p[i][h][2] = fmaf(v, sW3[cc * 3 + 2], p[i][h][2]);
            }
        }
    }
    #pragma unroll
    for (int i = 0; i < 2; ++i)
        #pragma unroll
        for (int h = 0; h < 2; ++h)
            #pragma unroll
            for (int o = 0; o < 3; ++o) {
                float v = p[i][h][o];
                v += __shfl_xor_sync(0xffffffffu, v, 1);
                v += __shfl_xor_sync(0xffffffffu, v, 2);
                p[i][h][o] = v;
            }
    __syncthreads();  // all fragment reads done; safe to write sPart
    if ((lane & 3) == 0) {
        const int cg = wid & 3;
        #pragma unroll
        for (int i = 0; i < 2; ++i)
            #pragma unroll
            for (int h = 0; h < 2; ++h) {
                const int r = m0 + i * 16 + (lane >> 2) + 8 * h;
                sPart[cg * 384 + r * 3 + 0] = p[i][h][0];
                sPart[cg * 384 + r * 3 + 1] = p[i][h][1];
                sPart[cg * 384 + r * 3 + 2] = p[i][h][2];
            }
    }
    __syncthreads();

    if (tid < 384) {
        const int r = tid / 3, o = tid - r * 3;
        out[(row0 + r) * 3 + o] =
            sPart[tid] + sPart[384 + tid] + sPart[768 + tid] + sPart[1152 + tid] + b3[o];
    }
}

// ============================================================================
// Launch
// ============================================================================
extern "C" void kernel_launch(void* const* d_in, const int* in_sizes, int n_in,
                              void* d_out, int out_size) {
    const float* coord = (const float*)d_in[0];
    const float* W0    = (const float*)d_in[1];
    const float* b0    = (const float*)d_in[2];
    const float* W1    = (const float*)d_in[3];
    const float* b1    = (const float*)d_in[4];
    const float* W2    = (const float*)d_in[5];
    const float* b2    = (const float*)d_in[6];
    const float* W3    = (const float*)d_in[7];
    const float* b3    = (const float*)d_in[8];
    float* out = (float*)d_out;

    static bool attr_set = false;
    if (!attr_set) {
        cudaFuncSetAttribute(fused_mlp_kernel,
                             cudaFuncAttributeMaxDynamicSharedMemorySize, SMEM_TOTAL);
        attr_set = true;
    }

    const int prep_elems = 512 * 1024 + 256 * 512;
    prep_weights<<<(prep_elems + 255) / 256, 256>>>(W1, W2);
    fused_mlp_kernel<<<N_CTAS, THREADS, SMEM_TOTAL>>>(coord, W0, b0, b1, b2, W3, b3, out);
}

// round 14
// speedup vs baseline: 1.9744x; 1.9744x over previous
#include <cuda_runtime.h>
#include <cuda_fp16.h>
#include <cstdint>

#define DEVINL __device__ __forceinline__

DEVINL uint32_t smem_u32(const void* p) {
    uint32_t a;
    asm("{ .reg .u64 t; cvta.to.shared.u64 t, %1; cvt.u32.u64 %0, t; }"
        : "=r"(a) : "l"(p));
    return a;
}

// 128B-row swizzle — verified conflict-free for ldmatrix.x4
#define SWZ(o) ((o) ^ (((o) >> 3) & 0x70))

DEVINL void ldsm_x4(uint32_t& r0, uint32_t& r1, uint32_t& r2, uint32_t& r3, uint32_t addr) {
    asm volatile("ldmatrix.sync.aligned.m8n8.x4.shared.b16 {%0,%1,%2,%3}, [%4];"
                 : "=r"(r0), "=r"(r1), "=r"(r2), "=r"(r3) : "r"(addr));
}

DEVINL void mma_16816(float* c, uint32_t a0, uint32_t a1, uint32_t a2, uint32_t a3,
                      uint32_t b0, uint32_t b1) {
    asm volatile(
        "mma.sync.aligned.m16n8k16.row.col.f32.f16.f16.f32 "
        "{%0,%1,%2,%3}, {%4,%5,%6,%7}, {%8,%9}, {%0,%1,%2,%3};"
        : "+f"(c[0]), "+f"(c[1]), "+f"(c[2]), "+f"(c[3])
        : "r"(a0), "r"(a1), "r"(a2), "r"(a3), "r"(b0), "r"(b1));
}

DEVINL void cp_async16(uint32_t smem_addr, const void* gptr) {
    asm volatile("cp.async.cg.shared.global [%0], [%1], 16;"
                 :: "r"(smem_addr), "l"(gptr));
}
#define CP_COMMIT() asm volatile("cp.async.commit_group;" ::: "memory")
#define CP_WAIT(n)  asm volatile("cp.async.wait_group %0;" :: "n"(n) : "memory")

// ============================================================================
// Problem constants
// ============================================================================
static constexpr int N_ROWS  = 262144;
static constexpr int M_TILE  = 128;
static constexpr int N_CTAS  = N_ROWS / M_TILE;  // 2048
static constexpr int THREADS = 512;              // 16 warps, 4m x 4n, 32x64 tiles

// fp16 transposed weights (scratch via device globals)
__device__ __align__(16) __half w1h_g[512 * 1024];  // [N=512][K=1024]
__device__ __align__(16) __half w2h_g[256 * 512];   // [N=256][K=512]

// ---------------- SMEM layout (bytes) ----------------
static constexpr int SM_COORD = 0;       // 128 x float2          = 1024
static constexpr int SM_W0    = 1024;    // 2048 f32              = 8192
static constexpr int SM_B0    = 9216;    // 1024 f32              = 4096
static constexpr int SM_B1    = 13312;   // 512 f32               = 2048
static constexpr int SM_B2    = 15360;   // 256 f32               = 1024
static constexpr int SM_W3    = 16384;   // 768 f32               = 3072  -> 19456
static constexpr int SM_H2    = 19456;   // 8 blocks x 16KB       = 131072 -> 150528
// A double buffer OVERLAYS H2 blocks 4-5 (those blocks are written only at the
// pass-1 epilogue, which is preceded by a barrier after the last A read)
static constexpr int SM_A0    = SM_H2 + 4 * 16384;   // A buf 0 (128x64 fp16)
static constexpr int SM_A1B   = SM_H2 + 5 * 16384;   // A buf 1
static constexpr int SM_PART  = 150528;  // layer-3 partials (region free now)
static constexpr int SM_BCH0  = 166912;  // 256x64 fp16 SWZ128    = 32768 -> 199680
static constexpr int SM_BCH1  = 199680;  // 256x64 fp16 SWZ128    = 32768 -> 232448
static constexpr int SMEM_TOTAL = 232448;

// ============================================================================
// Prep: transpose + fp16-convert W1, W2
// ============================================================================
__global__ void prep_weights(const float* __restrict__ W1, const float* __restrict__ W2) {
    int i = blockIdx.x * blockDim.x + threadIdx.x;
    if (i < 512 * 1024) {
        int n = i >> 10, k = i & 1023;
        w1h_g[i] = __float2half_rn(W1[k * 512 + n]);
    } else {
        int j = i - 512 * 1024;
        if (j < 256 * 512) {
            int n = j >> 9, k = j & 511;
            w2h_g[j] = __float2half_rn(W2[k * 256 + n]);
        }
    }
}

// ============================================================================
// Fused MLP: one CTA = 128 rows; 16 warps; A double-buffered, produce
// overlapped with MMA of the previous chunk
// ============================================================================
__global__ __launch_bounds__(THREADS, 1) void fused_mlp_kernel(
    const float* __restrict__ coord,
    const float* __restrict__ W0, const float* __restrict__ b0,
    const float* __restrict__ b1, const float* __restrict__ b2,
    const float* __restrict__ W3, const float* __restrict__ b3,
    float* __restrict__ out)
{
    extern __shared__ char smem[];
    const uint32_t sb = smem_u32(smem);
    const int tid  = threadIdx.x;
    const int wid  = tid >> 5;
    const int lane = tid & 31;
    const int row0 = blockIdx.x * M_TILE;

    float* sCoord = (float*)(smem + SM_COORD);
    float* sW0    = (float*)(smem + SM_W0);
    float* sB0    = (float*)(smem + SM_B0);
    float* sB1    = (float*)(smem + SM_B1);
    float* sB2    = (float*)(smem + SM_B2);
    float* sW3    = (float*)(smem + SM_W3);
    float* sPart  = (float*)(smem + SM_PART);

    // ---- preload constants + coord tile ----
    if (tid < 256) sCoord[tid] = coord[row0 * 2 + tid];
    for (int i = tid; i < 2048; i += THREADS) sW0[i] = W0[i];
    for (int i = tid; i < 1024; i += THREADS) sB0[i] = b0[i];
    if (tid < 512) sB1[tid] = b1[tid];
    if (tid < 256) sB2[tid] = b2[tid];
    for (int i = tid; i < 768;  i += THREADS) sW3[i] = W3[i];

    // ---- per-warp tile geometry: 4 row groups x 4 col groups ----
    const int m0  = (wid >> 2) * 32;    // warp row base (32 rows)
    const int n0w = (wid & 3) * 64;     // warp col base within a 256-col pass

    const int a_row = (lane & 7) + ((lane >> 3) & 1) * 8;
    const int a_kby = ((lane >> 4) & 1) * 16;
    const int b_row = (lane & 7) + ((lane >> 4) & 1) * 8;
    const int b_kby = ((lane >> 3) & 1) * 16;

    // layer0 producer mapping: warp -> 8 rows, lane -> col pair (lane-contig)
    const int jj2 = lane * 2;

    // B-chunk async copy: 2048 x 16B per chunk over 512 threads -> 4 each
    const int rowb = tid >> 3;           // 0..63, stride 64 across ii
    const int seg  = tid & 7;

    // prologue: first B1 chunk (pass 0, kc 0) into buffer 0
    {
        const __half* src = w1h_g + rowb * 1024 + seg * 8;
        #pragma unroll
        for (int ii = 0; ii < 4; ++ii)
            cp_async16(sb + SM_BCH0 + SWZ((uint32_t)((rowb + 64 * ii) * 128 + seg * 16)),
                       src + (64 * ii) * 1024);
        CP_COMMIT();
    }
    __syncthreads();   // constants + coord visible

    // produce A chunk gk=0 (h1 cols 0..63) into A buf 0
    {
        const float w0x = sW0[jj2],     w0y = sW0[1024 + jj2];
        const float w1x = sW0[jj2 + 1], w1y = sW0[1024 + jj2 + 1];
        const float bj0 = sB0[jj2],     bj1 = sB0[jj2 + 1];
        #pragma unroll
        for (int rr = 0; rr < 8; ++rr) {
            const int r = wid * 8 + rr;
            const float cx = sCoord[2 * r], cy = sCoord[2 * r + 1];
            float v0 = fmaxf(fmaf(cx, w0x, fmaf(cy, w0y, bj0)), 0.0f);
            float v1 = fmaxf(fmaf(cx, w1x, fmaf(cy, w1y, bj1)), 0.0f);
            *(__half2*)(smem + SM_A0 + SWZ((uint32_t)(r * 128 + jj2 * 2))) =
                __floats2half2_rn(v0, v1);
        }
    }

    // =========================================================================
    // Layer 0+1: D1[128,512] = relu(coord@W0+b0) @ W1, two 256-col passes
    //   A chunks double-buffered; produce(gk+1) overlaps MMA(gk)
    // =========================================================================
    for (int pass = 0; pass < 2; ++pass) {
        float acc[2][8][4];
        #pragma unroll
        for (int i = 0; i < 2; ++i)
            #pragma unroll
            for (int j = 0; j < 8; ++j)
                #pragma unroll
                for (int q = 0; q < 4; ++q) acc[i][j][q] = 0.f;

        for (int kc = 0; kc < 16; ++kc) {
            const int gk = pass * 16 + kc;           // global chunk index
            const uint32_t bcur = (gk & 1) ? SM_BCH1 : SM_BCH0;
            const uint32_t bnxt = (gk & 1) ? SM_BCH0 : SM_BCH1;
            const uint32_t acur = (gk & 1) ? SM_A1B : SM_A0;
            __syncthreads();  // buffer-reuse fence (prev MMA reads done)

            const bool last = (gk == 31);
            if (kc < 15) {
                const int j0n = (kc + 1) * 64;
                const __half* src = w1h_g + (pass * 256 + rowb) * 1024 + j0n + seg * 8;
                #pragma unroll
                for (int ii = 0; ii < 4; ++ii)
                    cp_async16(sb + bnxt + SWZ((uint32_t)((rowb + 64 * ii) * 128 + seg * 16)),
                               src + (64 * ii) * 1024);
                CP_COMMIT();
            } else if (pass == 0) {
                const __half* src = w1h_g + (256 + rowb) * 1024 + seg * 8;
                #pragma unroll
                for (int ii = 0; ii < 4; ++ii)
                    cp_async16(sb + bnxt + SWZ((uint32_t)((rowb + 64 * ii) * 128 + seg * 16)),
                               src + (64 * ii) * 1024);
                CP_COMMIT();
            }

            if (last) { CP_WAIT(0); } else { CP_WAIT(1); }
            __syncthreads();  // A(gk) stores + B(gk) arrival visible

            // --- 4 k-steps of mma ---
            #pragma unroll
            for (int ks = 0; ks < 4; ++ks) {
                const int kby = ks * 32;
                uint32_t A0r[4], A1r[4];
                ldsm_x4(A0r[0], A0r[1], A0r[2], A0r[3],
                        sb + acur + SWZ((uint32_t)((m0 + a_row) * 128 + kby + a_kby)));
                ldsm_x4(A1r[0], A1r[1], A1r[2], A1r[3],
                        sb + acur + SWZ((uint32_t)((m0 + 16 + a_row) * 128 + kby + a_kby)));
                #pragma unroll
                for (int j2 = 0; j2 < 4; ++j2) {
                    uint32_t bb[4];
                    ldsm_x4(bb[0], bb[1], bb[2], bb[3],
                            sb + bcur + SWZ((uint32_t)((n0w + j2 * 16 + b_row) * 128 + kby + b_kby)));
                    mma_16816(acc[0][2 * j2],     A0r[0], A0r[1], A0r[2], A0r[3], bb[0], bb[1]);
                    mma_16816(acc[0][2 * j2 + 1], A0r[0], A0r[1], A0r[2], A0r[3], bb[2], bb[3]);
                    mma_16816(acc[1][2 * j2],     A1r[0], A1r[1], A1r[2], A1r[3], bb[0], bb[1]);
                    mma_16816(acc[1][2 * j2 + 1], A1r[0], A1r[1], A1r[2], A1r[3], bb[2], bb[3]);
                }
            }

            // --- produce A(gk+1) into the other buffer; overlaps MMA above
            //     across warps (this warp's MMA is done; others still run) ---
            if (gk < 31) {
                const int j0p = ((gk + 1) & 15) * 64;   // h1 cols depend on kc only
                const uint32_t anxt = ((gk + 1) & 1) ? SM_A1B : SM_A0;
                const int j = j0p + jj2;
                const float w0x = sW0[j],     w0y = sW0[1024 + j];
                const float w1x = sW0[j + 1], w1y = sW0[1024 + j + 1];
                const float bj0 = sB0[j],     bj1 = sB0[j + 1];
                #pragma unroll
                for (int rr = 0; rr < 8; ++rr) {
                    const int r = wid * 8 + rr;
                    const float cx = sCoord[2 * r], cy = sCoord[2 * r + 1];
                    float v0 = fmaxf(fmaf(cx, w0x, fmaf(cy, w0y, bj0)), 0.0f);
                    float v1 = fmaxf(fmaf(cx, w1x, fmaf(cy, w1y, bj1)), 0.0f);
                    *(__half2*)(smem + anxt + SWZ((uint32_t)(r * 128 + jj2 * 2))) =
                        __floats2half2_rn(v0, v1);
                }
            }

            if (last) {
                // prologue for layer-2 (gk=31 -> bcur=BCH1, BCH0 free)
                const __half* src = w2h_g + rowb * 512 + seg * 8;
                #pragma unroll
                for (int ii = 0; ii < 4; ++ii)
                    cp_async16(sb + SM_BCH0 + SWZ((uint32_t)((rowb + 64 * ii) * 128 + seg * 16)),
                               src + (64 * ii) * 512);
                CP_COMMIT();
            }
        }

        // --- epilogue: h2 = relu(D1 + b1) -> fp16 H2 (8 x 16KB blocks) ---
        // pass 1 writes blocks 4-7 which overlay the A buffers: barrier first
        // so every warp's last A reads (chunk 31) are complete.
        if (pass == 1) __syncthreads();
        const int cn = pass * 256 + n0w;
        #pragma unroll
        for (int i = 0; i < 2; ++i) {
            const int r = m0 + i * 16 + (lane >> 2);
            #pragma unroll
            for (int j = 0; j < 8; ++j) {
                const int c = cn + j * 8 + (lane & 3) * 2;
                const float bz0 = sB1[c], bz1 = sB1[c + 1];
                float v0 = fmaxf(acc[i][j][0] + bz0, 0.f);
                float v1 = fmaxf(acc[i][j][1] + bz1, 0.f);
                float v2 = fmaxf(acc[i][j][2] + bz0, 0.f);
                float v3 = fmaxf(acc[i][j][3] + bz1, 0.f);
                const int blk = c >> 6, jj = (c & 63) * 2;
                *(__half2*)(smem + SM_H2 + blk * 16384 + SWZ((uint32_t)(r * 128 + jj))) =
                    __floats2half2_rn(v0, v1);
                *(__half2*)(smem + SM_H2 + blk * 16384 + SWZ((uint32_t)((r + 8) * 128 + jj))) =
                    __floats2half2_rn(v2, v3);
            }
        }
    }

    // =========================================================================
    // Layer 2: D2[128,256] = h2[128,512] @ W2 (A resident in SM_H2)
    // =========================================================================
    float acc2[2][8][4];
    #pragma unroll
    for (int i = 0; i < 2; ++i)
        #pragma unroll
        for (int j = 0; j < 8; ++j)
            #pragma unroll
            for (int q = 0; q < 4; ++q) acc2[i][j][q] = 0.f;

    for (int kc = 0; kc < 8; ++kc) {
        const uint32_t bcur = (kc & 1) ? SM_BCH1 : SM_BCH0;
        const uint32_t bnxt = (kc & 1) ? SM_BCH0 : SM_BCH1;
        __syncthreads();  // buffer-reuse fence + (kc==0) h2-write fence

        if (kc < 7) {
            const __half* src = w2h_g + rowb * 512 + (kc + 1) * 64 + seg * 8;
            #pragma unroll
            for (int ii = 0; ii < 4; ++ii)
                cp_async16(sb + bnxt + SWZ((uint32_t)((rowb + 64 * ii) * 128 + seg * 16)),
                           src + (64 * ii) * 512);
            CP_COMMIT();
            CP_WAIT(1);
        } else {
            CP_WAIT(0);
        }
        __syncthreads();

        const uint32_t abase = sb + SM_H2 + kc * 16384;
        #pragma unroll
        for (int ks = 0; ks < 4; ++ks) {
            const int kby = ks * 32;
            uint32_t A0r[4], A1r[4];
            ldsm_x4(A0r[0], A0r[1], A0r[2], A0r[3],
                    abase + SWZ((uint32_t)((m0 + a_row) * 128 + kby + a_kby)));
            ldsm_x4(A1r[0], A1r[1], A1r[2], A1r[3],
                    abase + SWZ((uint32_t)((m0 + 16 + a_row) * 128 + kby + a_kby)));
            #pragma unroll
            for (int j2 = 0; j2 < 4; ++j2) {
                uint32_t bb[4];
                ldsm_x4(bb[0], bb[1], bb[2], bb[3],
                        sb + bcur + SWZ((uint32_t)((n0w + j2 * 16 + b_row) * 128 + kby + b_kby)));
                mma_16816(acc2[0][2 * j2],     A0r[0], A0r[1], A0r[2], A0r[3], bb[0], bb[1]);
                mma_16816(acc2[0][2 * j2 + 1], A0r[0], A0r[1], A0r[2], A0r[3], bb[2], bb[3]);
                mma_16816(acc2[1][2 * j2],     A1r[0], A1r[1], A1r[2], A1r[3], bb[0], bb[1]);
                mma_16816(acc2[1][2 * j2 + 1], A1r[0], A1r[1], A1r[2], A1r[3], bb[2], bb[3]);
            }
        }
    }

    // =========================================================================
    // Layer 3: out = relu(D2 + b2) @ W3 + b3, from register fragments
    // =========================================================================
    float p[2][2][3];
    #pragma unroll
    for (int i = 0; i < 2; ++i)
        #pragma unroll
        for (int h = 0; h < 2; ++h)
            p[i][h][0] = p[i][h][1] = p[i][h][2] = 0.f;

    #pragma unroll
    for (int i = 0; i < 2; ++i) {
        #pragma unroll
        for (int j = 0; j < 8; ++j) {
            const int c = n0w + j * 8 + (lane & 3) * 2;
            #pragma unroll
            for (int q = 0; q < 4; ++q) {
                const int h  = q >> 1;
                const int cc = c + (q & 1);
                const float v = fmaxf(acc2[i][j][q] + sB2[cc], 0.f);
                p[i][h][0] = fmaf(v, sW3[cc * 3 + 0], p[i][h][0]);
                p[i][h][1] = fmaf(v, sW3[cc * 3 + 1], p[i][h][1]);
                p[i][h][2] = fmaf(v, sW3[cc * 3 + 2], p[i][h][2]);
            }
        }
    }
    #pragma unroll
    for (int i = 0; i < 2; ++i)
        #pragma unroll
        for (int h = 0; h < 2; ++h)
            #pragma unroll
            for (int o = 0; o < 3; ++o) {
                float v = p[i][h][o];
                v += __shfl_xor_sync(0xffffffffu, v, 1);
                v += __shfl_xor_sync(0xffffffffu, v, 2);
                p[i][h][o] = v;
            }
    __syncthreads();  // all fragment reads done before sPart writes
    if ((lane & 3) == 0) {
        const int cg = wid & 3;
        #pragma unroll
        for (int i = 0; i < 2; ++i)
            #pragma unroll
            for (int h = 0; h < 2; ++h) {
                const int r = m0 + i * 16 + (lane >> 2) + 8 * h;
                sPart[cg * 384 + r * 3 + 0] = p[i][h][0];
                sPart[cg * 384 + r * 3 + 1] = p[i][h][1];
                sPart[cg * 384 + r * 3 + 2] = p[i][h][2];
            }
    }
    __syncthreads();

    if (tid < 384) {
        const int r = tid / 3, o = tid - r * 3;
        out[(row0 + r) * 3 + o] =
            sPart[tid] + sPart[384 + tid] + sPart[768 + tid] + sPart[1152 + tid] + b3[o];
    }
}

// ============================================================================
// Launch
// ============================================================================
extern "C" void kernel_launch(void* const* d_in, const int* in_sizes, int n_in,
                              void* d_out, int out_size) {
    const float* coord = (const float*)d_in[0];
    const float* W0    = (const float*)d_in[1];
    const float* b0    = (const float*)d_in[2];
    const float* W1    = (const float*)d_in[3];
    const float* b1    = (const float*)d_in[4];
    const float* W2    = (const float*)d_in[5];
    const float* b2    = (const float*)d_in[6];
    const float* W3    = (const float*)d_in[7];
    const float* b3    = (const float*)d_in[8];
    float* out = (float*)d_out;

    static bool attr_set = false;
    if (!attr_set) {
        cudaFuncSetAttribute(fused_mlp_kernel,
                             cudaFuncAttributeMaxDynamicSharedMemorySize, SMEM_TOTAL);
        attr_set = true;
    }

    const int prep_elems = 512 * 1024 + 256 * 512;
    prep_weights<<<(prep_elems + 255) / 256, 256>>>(W1, W2);
    fused_mlp_kernel<<<N_CTAS, THREADS, SMEM_TOTAL>>>(coord, W0, b0, b1, b2, W3, b3, out);
}

// round 15
// speedup vs baseline: 2.0353x; 1.0308x over previous
#include <cuda_runtime.h>
#include <cuda_fp16.h>
#include <cstdint>

#define DEVINL __device__ __forceinline__

DEVINL uint32_t smem_u32(const void* p) {
    uint32_t a;
    asm("{ .reg .u64 t; cvta.to.shared.u64 t, %1; cvt.u32.u64 %0, t; }"
        : "=r"(a) : "l"(p));
    return a;
}

// 128B-row swizzle — verified conflict-free for ldmatrix.x4
#define SWZ(o) ((o) ^ (((o) >> 3) & 0x70))

DEVINL void ldsm_x4(uint32_t& r0, uint32_t& r1, uint32_t& r2, uint32_t& r3, uint32_t addr) {
    asm volatile("ldmatrix.sync.aligned.m8n8.x4.shared.b16 {%0,%1,%2,%3}, [%4];"
                 : "=r"(r0), "=r"(r1), "=r"(r2), "=r"(r3) : "r"(addr));
}

DEVINL void mma_16816(float* c, uint32_t a0, uint32_t a1, uint32_t a2, uint32_t a3,
                      uint32_t b0, uint32_t b1) {
    asm volatile(
        "mma.sync.aligned.m16n8k16.row.col.f32.f16.f16.f32 "
        "{%0,%1,%2,%3}, {%4,%5,%6,%7}, {%8,%9}, {%0,%1,%2,%3};"
        : "+f"(c[0]), "+f"(c[1]), "+f"(c[2]), "+f"(c[3])
        : "r"(a0), "r"(a1), "r"(a2), "r"(a3), "r"(b0), "r"(b1));
}

DEVINL void cp_async16(uint32_t smem_addr, const void* gptr) {
    asm volatile("cp.async.cg.shared.global [%0], [%1], 16;"
                 :: "r"(smem_addr), "l"(gptr));
}
#define CP_COMMIT() asm volatile("cp.async.commit_group;" ::: "memory")
#define CP_WAIT(n)  asm volatile("cp.async.wait_group %0;" :: "n"(n) : "memory")

// ============================================================================
// Problem constants
// ============================================================================
static constexpr int N_ROWS  = 262144;
static constexpr int M_TILE  = 128;
static constexpr int N_CTAS  = N_ROWS / M_TILE;  // 2048
static constexpr int THREADS = 512;              // 16 warps, 4m x 4n, 32x64 tiles

// fp16 transposed weights (scratch via device globals)
__device__ __align__(16) __half w1h_g[512 * 1024];  // [N=512][K=1024]
__device__ __align__(16) __half w2h_g[256 * 512];   // [N=256][K=512]

// ---------------- SMEM layout (bytes) ----------------
static constexpr int SM_COORD = 0;       // 128 x float2          = 1024
static constexpr int SM_W0    = 1024;    // 2048 f32              = 8192
static constexpr int SM_B0    = 9216;    // 1024 f32              = 4096
static constexpr int SM_B1    = 13312;   // 512 f32               = 2048
static constexpr int SM_B2    = 15360;   // 256 f32               = 1024
static constexpr int SM_W3    = 16384;   // 768 f32               = 3072  -> 19456
static constexpr int SM_H2    = 19456;   // 8 blocks x 16KB       = 131072 -> 150528
// A double buffer OVERLAYS H2 blocks 4-5 (written only at pass-1 epilogue,
// which is preceded by a barrier after the last A read)
static constexpr int SM_A0    = SM_H2 + 4 * 16384;   // A buf 0 (128x64 fp16)
static constexpr int SM_A1B   = SM_H2 + 5 * 16384;   // A buf 1
static constexpr int SM_PART  = 150528;  // layer-3 partials
static constexpr int SM_BCH0  = 166912;  // 256x64 fp16 SWZ128    = 32768 -> 199680
static constexpr int SM_BCH1  = 199680;  // 256x64 fp16 SWZ128    = 32768 -> 232448
static constexpr int SMEM_TOTAL = 232448;

// ============================================================================
// Prep: transpose + fp16-convert W1, W2
// ============================================================================
__global__ void prep_weights(const float* __restrict__ W1, const float* __restrict__ W2) {
    int i = blockIdx.x * blockDim.x + threadIdx.x;
    if (i < 512 * 1024) {
        int n = i >> 10, k = i & 1023;
        w1h_g[i] = __float2half_rn(W1[k * 512 + n]);
    } else {
        int j = i - 512 * 1024;
        if (j < 256 * 512) {
            int n = j >> 9, k = j & 511;
            w2h_g[j] = __float2half_rn(W2[k * 256 + n]);
        }
    }
}

// ============================================================================
// Fused MLP: one CTA = 128 rows; 16 warps; SINGLE barrier per chunk
// (wait -> barrier -> issue -> MMA+produce)
// ============================================================================
__global__ __launch_bounds__(THREADS, 1) void fused_mlp_kernel(
    const float* __restrict__ coord,
    const float* __restrict__ W0, const float* __restrict__ b0,
    const float* __restrict__ b1, const float* __restrict__ b2,
    const float* __restrict__ W3, const float* __restrict__ b3,
    float* __restrict__ out)
{
    extern __shared__ char smem[];
    const uint32_t sb = smem_u32(smem);
    const int tid  = threadIdx.x;
    const int wid  = tid >> 5;
    const int lane = tid & 31;
    const int row0 = blockIdx.x * M_TILE;

    float* sCoord = (float*)(smem + SM_COORD);
    float* sW0    = (float*)(smem + SM_W0);
    float* sB0    = (float*)(smem + SM_B0);
    float* sB1    = (float*)(smem + SM_B1);
    float* sB2    = (float*)(smem + SM_B2);
    float* sW3    = (float*)(smem + SM_W3);
    float* sPart  = (float*)(smem + SM_PART);

    // ---- preload constants + coord tile ----
    if (tid < 256) sCoord[tid] = coord[row0 * 2 + tid];
    for (int i = tid; i < 2048; i += THREADS) sW0[i] = W0[i];
    for (int i = tid; i < 1024; i += THREADS) sB0[i] = b0[i];
    if (tid < 512) sB1[tid] = b1[tid];
    if (tid < 256) sB2[tid] = b2[tid];
    for (int i = tid; i < 768;  i += THREADS) sW3[i] = W3[i];

    // ---- per-warp tile geometry: 4 row groups x 4 col groups ----
    const int m0  = (wid >> 2) * 32;    // warp row base (32 rows)
    const int n0w = (wid & 3) * 64;     // warp col base within a 256-col pass

    const int a_row = (lane & 7) + ((lane >> 3) & 1) * 8;
    const int a_kby = ((lane >> 4) & 1) * 16;
    const int b_row = (lane & 7) + ((lane >> 4) & 1) * 8;
    const int b_kby = ((lane >> 3) & 1) * 16;

    // layer0 producer mapping: warp -> 8 rows, lane -> col pair (lane-contig)
    const int jj2 = lane * 2;

    // B-chunk async copy: 2048 x 16B per chunk over 512 threads -> 4 each
    const int rowb = tid >> 3;           // 0..63, stride 64 across ii
    const int seg  = tid & 7;

    // prologue: first B1 chunk (pass 0, kc 0) into buffer 0
    {
        const __half* src = w1h_g + rowb * 1024 + seg * 8;
        #pragma unroll
        for (int ii = 0; ii < 4; ++ii)
            cp_async16(sb + SM_BCH0 + SWZ((uint32_t)((rowb + 64 * ii) * 128 + seg * 16)),
                       src + (64 * ii) * 1024);
        CP_COMMIT();
    }
    __syncthreads();   // constants + coord visible

    // produce A chunk gk=0 (h1 cols 0..63) into A buf 0
    {
        const float w0x = sW0[jj2],     w0y = sW0[1024 + jj2];
        const float w1x = sW0[jj2 + 1], w1y = sW0[1024 + jj2 + 1];
        const float bj0 = sB0[jj2],     bj1 = sB0[jj2 + 1];
        #pragma unroll
        for (int rr = 0; rr < 8; ++rr) {
            const int r = wid * 8 + rr;
            const float cx = sCoord[2 * r], cy = sCoord[2 * r + 1];
            float v0 = fmaxf(fmaf(cx, w0x, fmaf(cy, w0y, bj0)), 0.0f);
            float v1 = fmaxf(fmaf(cx, w1x, fmaf(cy, w1y, bj1)), 0.0f);
            *(__half2*)(smem + SM_A0 + SWZ((uint32_t)(r * 128 + jj2 * 2))) =
                __floats2half2_rn(v0, v1);
        }
    }

    // =========================================================================
    // Layer 0+1: D1[128,512] = relu(coord@W0+b0) @ W1, two 256-col passes
    //   Single barrier per chunk: WAIT(0) -> bar -> issue(g+1) -> MMA + produce
    // =========================================================================
    for (int pass = 0; pass < 2; ++pass) {
        float acc[2][8][4];
        #pragma unroll
        for (int i = 0; i < 2; ++i)
            #pragma unroll
            for (int j = 0; j < 8; ++j)
                #pragma unroll
                for (int q = 0; q < 4; ++q) acc[i][j][q] = 0.f;

        for (int kc = 0; kc < 16; ++kc) {
            const int gk = pass * 16 + kc;           // global chunk index
            const uint32_t bcur = (gk & 1) ? SM_BCH1 : SM_BCH0;
            const uint32_t bnxt = (gk & 1) ? SM_BCH0 : SM_BCH1;
            const uint32_t acur = (gk & 1) ? SM_A1B : SM_A0;

            CP_WAIT(0);       // chunk gk (issued last iteration) complete
            __syncthreads();  // publish B(gk)+A(gk); fence reads of gk-1

            // issue next B chunk into the buffer just freed (overlaps MMA)
            if (kc < 15) {
                const int j0n = (kc + 1) * 64;
                const __half* src = w1h_g + (pass * 256 + rowb) * 1024 + j0n + seg * 8;
                #pragma unroll
                for (int ii = 0; ii < 4; ++ii)
                    cp_async16(sb + bnxt + SWZ((uint32_t)((rowb + 64 * ii) * 128 + seg * 16)),
                               src + (64 * ii) * 1024);
                CP_COMMIT();
            } else if (pass == 0) {
                const __half* src = w1h_g + (256 + rowb) * 1024 + seg * 8;
                #pragma unroll
                for (int ii = 0; ii < 4; ++ii)
                    cp_async16(sb + bnxt + SWZ((uint32_t)((rowb + 64 * ii) * 128 + seg * 16)),
                               src + (64 * ii) * 1024);
                CP_COMMIT();
            } else {
                // gk == 31: first W2 chunk into bnxt (= BCH0)
                const __half* src = w2h_g + rowb * 512 + seg * 8;
                #pragma unroll
                for (int ii = 0; ii < 4; ++ii)
                    cp_async16(sb + bnxt + SWZ((uint32_t)((rowb + 64 * ii) * 128 + seg * 16)),
                               src + (64 * ii) * 512);
                CP_COMMIT();
            }

            // --- 4 k-steps of mma ---
            #pragma unroll
            for (int ks = 0; ks < 4; ++ks) {
                const int kby = ks * 32;
                uint32_t A0r[4], A1r[4];
                ldsm_x4(A0r[0], A0r[1], A0r[2], A0r[3],
                        sb + acur + SWZ((uint32_t)((m0 + a_row) * 128 + kby + a_kby)));
                ldsm_x4(A1r[0], A1r[1], A1r[2], A1r[3],
                        sb + acur + SWZ((uint32_t)((m0 + 16 + a_row) * 128 + kby + a_kby)));
                #pragma unroll
                for (int j2 = 0; j2 < 4; ++j2) {
                    uint32_t bb[4];
                    ldsm_x4(bb[0], bb[1], bb[2], bb[3],
                            sb + bcur + SWZ((uint32_t)((n0w + j2 * 16 + b_row) * 128 + kby + b_kby)));
                    mma_16816(acc[0][2 * j2],     A0r[0], A0r[1], A0r[2], A0r[3], bb[0], bb[1]);
                    mma_16816(acc[0][2 * j2 + 1], A0r[0], A0r[1], A0r[2], A0r[3], bb[2], bb[3]);
                    mma_16816(acc[1][2 * j2],     A1r[0], A1r[1], A1r[2], A1r[3], bb[0], bb[1]);
                    mma_16816(acc[1][2 * j2 + 1], A1r[0], A1r[1], A1r[2], A1r[3], bb[2], bb[3]);
                }
            }

            // --- produce A(gk+1) into the other buffer (read after next bar) ---
            if (gk < 31) {
                const int j0p = ((gk + 1) & 15) * 64;   // h1 cols depend on kc only
                const uint32_t anxt = ((gk + 1) & 1) ? SM_A1B : SM_A0;
                const int j = j0p + jj2;
                const float w0x = sW0[j],     w0y = sW0[1024 + j];
                const float w1x = sW0[j + 1], w1y = sW0[1024 + j + 1];
                const float bj0 = sB0[j],     bj1 = sB0[j + 1];
                #pragma unroll
                for (int rr = 0; rr < 8; ++rr) {
                    const int r = wid * 8 + rr;
                    const float cx = sCoord[2 * r], cy = sCoord[2 * r + 1];
                    float v0 = fmaxf(fmaf(cx, w0x, fmaf(cy, w0y, bj0)), 0.0f);
                    float v1 = fmaxf(fmaf(cx, w1x, fmaf(cy, w1y, bj1)), 0.0f);
                    *(__half2*)(smem + anxt + SWZ((uint32_t)(r * 128 + jj2 * 2))) =
                        __floats2half2_rn(v0, v1);
                }
            }
        }

        // --- epilogue: h2 = relu(D1 + b1) -> fp16 H2 (8 x 16KB blocks) ---
        // pass 1 writes blocks 4-7 which overlay the A buffers: barrier first
        // so every warp's last A reads (chunk 31) are complete.
        if (pass == 1) __syncthreads();
        const int cn = pass * 256 + n0w;
        #pragma unroll
        for (int i = 0; i < 2; ++i) {
            const int r = m0 + i * 16 + (lane >> 2);
            #pragma unroll
            for (int j = 0; j < 8; ++j) {
                const int c = cn + j * 8 + (lane & 3) * 2;
                const float bz0 = sB1[c], bz1 = sB1[c + 1];
                float v0 = fmaxf(acc[i][j][0] + bz0, 0.f);
                float v1 = fmaxf(acc[i][j][1] + bz1, 0.f);
                float v2 = fmaxf(acc[i][j][2] + bz0, 0.f);
                float v3 = fmaxf(acc[i][j][3] + bz1, 0.f);
                const int blk = c >> 6, jj = (c & 63) * 2;
                *(__half2*)(smem + SM_H2 + blk * 16384 + SWZ((uint32_t)(r * 128 + jj))) =
                    __floats2half2_rn(v0, v1);
                *(__half2*)(smem + SM_H2 + blk * 16384 + SWZ((uint32_t)((r + 8) * 128 + jj))) =
                    __floats2half2_rn(v2, v3);
            }
        }
    }

    // =========================================================================
    // Layer 2: D2[128,256] = h2[128,512] @ W2 (A resident in SM_H2)
    //   Same single-barrier scheme.
    // =========================================================================
    float acc2[2][8][4];
    #pragma unroll
    for (int i = 0; i < 2; ++i)
        #pragma unroll
        for (int j = 0; j < 8; ++j)
            #pragma unroll
            for (int q = 0; q < 4; ++q) acc2[i][j][q] = 0.f;

    for (int kc = 0; kc < 8; ++kc) {
        const uint32_t bcur = (kc & 1) ? SM_BCH1 : SM_BCH0;
        const uint32_t bnxt = (kc & 1) ? SM_BCH0 : SM_BCH1;

        CP_WAIT(0);       // W2 chunk kc complete
        __syncthreads();  // publish it (+ h2 epilogue writes when kc==0)

        if (kc < 7) {
            const __half* src = w2h_g + rowb * 512 + (kc + 1) * 64 + seg * 8;
            #pragma unroll
            for (int ii = 0; ii < 4; ++ii)
                cp_async16(sb + bnxt + SWZ((uint32_t)((rowb + 64 * ii) * 128 + seg * 16)),
                           src + (64 * ii) * 512);
            CP_COMMIT();
        }

        const uint32_t abase = sb + SM_H2 + kc * 16384;
        #pragma unroll
        for (int ks = 0; ks < 4; ++ks) {
            const int kby = ks * 32;
            uint32_t A0r[4], A1r[4];
            ldsm_x4(A0r[0], A0r[1], A0r[2], A0r[3],
                    abase + SWZ((uint32_t)((m0 + a_row) * 128 + kby + a_kby)));
            ldsm_x4(A1r[0], A1r[1], A1r[2], A1r[3],
                    abase + SWZ((uint32_t)((m0 + 16 + a_row) * 128 + kby + a_kby)));
            #pragma unroll
            for (int j2 = 0; j2 < 4; ++j2) {
                uint32_t bb[4];
                ldsm_x4(bb[0], bb[1], bb[2], bb[3],
                        sb + bcur + SWZ((uint32_t)((n0w + j2 * 16 + b_row) * 128 + kby + b_kby)));
                mma_16816(acc2[0][2 * j2],     A0r[0], A0r[1], A0r[2], A0r[3], bb[0], bb[1]);
                mma_16816(acc2[0][2 * j2 + 1], A0r[0], A0r[1], A0r[2], A0r[3], bb[2], bb[3]);
                mma_16816(acc2[1][2 * j2],     A1r[0], A1r[1], A1r[2], A1r[3], bb[0], bb[1]);
                mma_16816(acc2[1][2 * j2 + 1], A1r[0], A1r[1], A1r[2], A1r[3], bb[2], bb[3]);
            }
        }
    }

    // =========================================================================
    // Layer 3: out = relu(D2 + b2) @ W3 + b3, from register fragments
    // =========================================================================
    float p[2][2][3];
    #pragma unroll
    for (int i = 0; i < 2; ++i)
        #pragma unroll
        for (int h = 0; h < 2; ++h)
            p[i][h][0] = p[i][h][1] = p[i][h][2] = 0.f;

    #pragma unroll
    for (int i = 0; i < 2; ++i) {
        #pragma unroll
        for (int j = 0; j < 8; ++j) {
            const int c = n0w + j * 8 + (lane & 3) * 2;
            #pragma unroll
            for (int q = 0; q < 4; ++q) {
                const int h  = q >> 1;
                const int cc = c + (q & 1);
                const float v = fmaxf(acc2[i][j][q] + sB2[cc], 0.f);
                p[i][h][0] = fmaf(v, sW3[cc * 3 + 0], p[i][h][0]);
                p[i][h][1] = fmaf(v, sW3[cc * 3 + 1], p[i][h][1]);
                p[i][h][2] = fmaf(v, sW3[cc * 3 + 2], p[i][h][2]);
            }
        }
    }
    #pragma unroll
    for (int i = 0; i < 2; ++i)
        #pragma unroll
        for (int h = 0; h < 2; ++h)
            #pragma unroll
            for (int o = 0; o < 3; ++o) {
                float v = p[i][h][o];
                v += __shfl_xor_sync(0xffffffffu, v, 1);
                v += __shfl_xor_sync(0xffffffffu, v, 2);
                p[i][h][o] = v;
            }
    __syncthreads();  // all fragment reads done before sPart writes
    if ((lane & 3) == 0) {
        const int cg = wid & 3;
        #pragma unroll
        for (int i = 0; i < 2; ++i)
            #pragma unroll
            for (int h = 0; h < 2; ++h) {
                const int r = m0 + i * 16 + (lane >> 2) + 8 * h;
                sPart[cg * 384 + r * 3 + 0] = p[i][h][0];
                sPart[cg * 384 + r * 3 + 1] = p[i][h][1];
                sPart[cg * 384 + r * 3 + 2] = p[i][h][2];
            }
    }
    __syncthreads();

    if (tid < 384) {
        const int r = tid / 3, o = tid - r * 3;
        out[(row0 + r) * 3 + o] =
            sPart[tid] + sPart[384 + tid] + sPart[768 + tid] + sPart[1152 + tid] + b3[o];
    }
}

// ============================================================================
// Launch
// ============================================================================
extern "C" void kernel_launch(void* const* d_in, const int* in_sizes, int n_in,
                              void* d_out, int out_size) {
    const float* coord = (const float*)d_in[0];
    const float* W0    = (const float*)d_in[1];
    const float* b0    = (const float*)d_in[2];
    const float* W1    = (const float*)d_in[3];
    const float* b1    = (const float*)d_in[4];
    const float* W2    = (const float*)d_in[5];
    const float* b2    = (const float*)d_in[6];
    const float* W3    = (const float*)d_in[7];
    const float* b3    = (const float*)d_in[8];
    float* out = (float*)d_out;

    static bool attr_set = false;
    if (!attr_set) {
        cudaFuncSetAttribute(fused_mlp_kernel,
                             cudaFuncAttributeMaxDynamicSharedMemorySize, SMEM_TOTAL);
        attr_set = true;
    }

    const int prep_elems = 512 * 1024 + 256 * 512;
    prep_weights<<<(prep_elems + 255) / 256, 256>>>(W1, W2);
    fused_mlp_kernel<<<N_CTAS, THREADS, SMEM_TOTAL>>>(coord, W0, b0, b1, b2, W3, b3, out);
}